// round 10
// baseline (speedup 1.0000x reference)
#include <cuda_runtime.h>
#include <math.h>
#include <cstdint>

// Problem constants (hardcoded in reference)
#define B 32
#define D 128
#define K 512
#define C 10
#define NT 1024
#define NFLAGPAD 12       // 10 flags padded to 12 for v4 polling

// Cross-CTA state
__device__ float g_fac2[C][K];
__device__ __align__(16) int g_pflag[NFLAGPAD];  // [10] used, [10..11] always 0
__device__ int g_done = 0;                        // consumers done (target B)

__device__ __forceinline__ void st_release_gpu(int* p, int v) {
    asm volatile("st.release.gpu.global.s32 [%0], %1;" :: "l"(p), "r"(v) : "memory");
}
__device__ __forceinline__ int4 ld_volatile_v4(const int4* p) {
    int4 v;
    asm volatile("ld.volatile.global.v4.s32 {%0,%1,%2,%3}, [%4];"
                 : "=r"(v.x), "=r"(v.y), "=r"(v.z), "=r"(v.w) : "l"(p) : "memory");
    return v;
}
__device__ __forceinline__ void fence_acq_rel_gpu() {
    asm volatile("fence.acq_rel.gpu;" ::: "memory");
}
// Packed f32x2 helpers (Blackwell FFMA2 — PTX-only, ptxas never auto-fuses)
__device__ __forceinline__ uint64_t pack2(float v) {
    uint64_t r;
    asm("mov.b64 %0, {%1, %1};" : "=l"(r) : "f"(v));
    return r;
}
__device__ __forceinline__ void fma2(uint64_t& d, uint64_t a, uint64_t b) {
    asm("fma.rn.f32x2 %0, %1, %2, %0;" : "+l"(d) : "l"(a), "l"(b));
}
__device__ __forceinline__ void add2(uint64_t& d, uint64_t a) {
    asm("add.rn.f32x2 %0, %0, %1;" : "+l"(d) : "l"(a));
}

// 42 CTAs x 1024 threads (one CTA per SM, single wave):
//   CTA 0..31  : consumer b — fac1 row in smem partials, poll flags,
//                warp-per-class dot, parallel softmax, write out[b].
//   CTA 32..41 : producer c — fac2 row, publish slice + release flag.
__global__ __launch_bounds__(NT, 1) void fused_kernel(
    const float* __restrict__ x,
    const float* __restrict__ mu,
    const float* __restrict__ U,
    const float* __restrict__ V,
    float* __restrict__ out) {
    __shared__ float sx[D];
    __shared__ float part[8][K];     // 8 d-groups x 512 (16 KB)
    __shared__ float f1s[K];
    __shared__ float hrow[C];

    const int t    = threadIdx.x;
    const int w    = t >> 5;
    const int lane = t & 31;
    const int g    = t >> 7;         // d-group 0..7 (16 d-rows each)
    const int tt   = t & 127;        // float4 col, full K

    const bool producer = (blockIdx.x >= B);
    const int  row = producer ? (blockIdx.x - B) : blockIdx.x;
    const float* src = producer ? (mu + row * D) : (x + row * D);
    const float* Wg  = (producer ? V : U) + g * 16 * K;

    if (t < D) sx[t] = src[t];

    // front-batched: all 16 LDG.128 in flight before the smem-operand wait
    ulonglong2 wv[16];
#pragma unroll
    for (int i = 0; i < 16; i++)
        wv[i] = reinterpret_cast<const ulonglong2*>(Wg + i * K)[tt];
    __syncthreads();

    // phase 1: packed f32x2 FMA chain (32 FFMA2 + 16 packs vs 64 FFMA)
    uint64_t a0 = 0, a1 = 0;         // bit pattern 0 == (0.0f, 0.0f)
    const float* sg = sx + g * 16;
#pragma unroll
    for (int i = 0; i < 16; i++) {
        const uint64_t s2 = pack2(sg[i]);
        fma2(a0, wv[i].x, s2);
        fma2(a1, wv[i].y, s2);
    }
    {
        ulonglong2 st2; st2.x = a0; st2.y = a1;
        *reinterpret_cast<ulonglong2*>(&part[g][tt * 4]) = st2;
    }
    __syncthreads();

    if (producer) {
        // reduce 8 d-partials (packed adds), publish fac2 row, release flag
        if (t < 128) {
            uint64_t r0 = 0, r1 = 0;
#pragma unroll
            for (int gg = 0; gg < 8; gg++) {
                ulonglong2 a = *reinterpret_cast<const ulonglong2*>(&part[gg][t * 4]);
                add2(r0, a.x);
                add2(r1, a.y);
            }
            ulonglong2 st2; st2.x = r0; st2.y = r1;
            reinterpret_cast<ulonglong2*>(&g_fac2[row][0])[t] = st2;
        }
        __syncthreads();                 // row stores happen-before flag
        if (t == 0) st_release_gpu(&g_pflag[row], 1);
        return;
    }

    // ---------------- consumer ----------------
    // fold d-group partials while thread 0 polls in parallel
    if (t == 0) {
        const int4* fp = reinterpret_cast<const int4*>(g_pflag);
        for (;;) {
            int4 f0 = ld_volatile_v4(fp);
            int4 f1 = ld_volatile_v4(fp + 1);
            int4 f2 = ld_volatile_v4(fp + 2);
            if (f0.x + f0.y + f0.z + f0.w + f1.x + f1.y + f1.z + f1.w +
                f2.x + f2.y + f2.z + f2.w == C) break;
        }
        fence_acq_rel_gpu();
    }
    if (t >= 512 && t < 768) {           // 256 threads fold 2 k's each (packed)
        const int k2 = (t - 512);        // float2 index 0..255
        uint64_t f = 0;
#pragma unroll
        for (int gg = 0; gg < 8; gg++)
            add2(f, reinterpret_cast<const uint64_t*>(&part[gg][0])[k2]);
        reinterpret_cast<uint64_t*>(f1s)[k2] = f;
    }
    __syncthreads();                     // f1s ready AND fac2 visible

    // one warp per class: dot(f1s, fac2[c]) over K=512 (4 x f32x2x2 per lane)
    if (w < C) {
        const ulonglong2* fa = reinterpret_cast<const ulonglong2*>(f1s);
        const ulonglong2* fb = reinterpret_cast<const ulonglong2*>(&g_fac2[w][0]);
        uint64_t p2 = 0;
#pragma unroll
        for (int j = 0; j < 4; j++) {
            const int i4 = lane + j * 32;
            ulonglong2 a = fa[i4];
            ulonglong2 b2 = fb[i4];
            fma2(p2, a.x, b2.x);
            fma2(p2, a.y, b2.y);
        }
        float plo, phi;
        asm("mov.b64 {%0, %1}, %2;" : "=f"(plo), "=f"(phi) : "l"(p2));
        float p = plo + phi;
#pragma unroll
        for (int o = 16; o > 0; o >>= 1)
            p += __shfl_xor_sync(0xffffffffu, p, o);
        if (lane == 0) hrow[w] = p;
    }
    __syncthreads();

    // parallel log_softmax in warp 0: lane c owns class c
    if (w == 0) {
        float h = (lane < C) ? hrow[lane] : -INFINITY;
        float m = h;
#pragma unroll
        for (int o = 8; o > 0; o >>= 1)
            m = fmaxf(m, __shfl_xor_sync(0xffffffffu, m, o));
        m = __shfl_sync(0xffffffffu, m, 0);
        float e = (lane < C) ? expf(h - m) : 0.f;
        float se = e;
#pragma unroll
        for (int o = 8; o > 0; o >>= 1)
            se += __shfl_xor_sync(0xffffffffu, se, o);
        se = __shfl_sync(0xffffffffu, se, 0);
        const float lse = m + logf(se);
        if (lane < C) out[row * C + lane] = h - lse;

        // last consumer resets flags for the next graph replay
        if (lane == 0 && atomicAdd(&g_done, 1) == B - 1) {
#pragma unroll
            for (int j = 0; j < C; j++) g_pflag[j] = 0;
            g_done = 0;
        }
    }
}

extern "C" void kernel_launch(void* const* d_in, const int* in_sizes, int n_in,
                              void* d_out, int out_size) {
    const float* x  = (const float*)d_in[0];  // [32, 128]
    const float* mu = (const float*)d_in[1];  // [10, 128]
    const float* U  = (const float*)d_in[2];  // [128, 512]
    const float* V  = (const float*)d_in[3];  // [128, 512]
    float* out = (float*)d_out;               // [32, 10]

    fused_kernel<<<B + C, NT>>>(x, mu, U, V, out);
}

// round 11
// speedup vs baseline: 1.0426x; 1.0426x over previous
#include <cuda_runtime.h>
#include <math.h>

// Problem constants (hardcoded in reference)
#define B 32
#define D 128
#define K 512
#define C 10
#define NT 1024
#define NFLAGPAD 12       // 10 flags padded to 12 for v4 polling

// Cross-CTA state
__device__ float g_fac2[C][K];
__device__ __align__(16) int g_pflag[NFLAGPAD];  // [10] used, [10..11] always 0
__device__ int g_done = 0;                        // consumers done (target B)

__device__ __forceinline__ void st_release_gpu(int* p, int v) {
    asm volatile("st.release.gpu.global.s32 [%0], %1;" :: "l"(p), "r"(v) : "memory");
}
__device__ __forceinline__ int4 ld_volatile_v4(const int4* p) {
    int4 v;
    asm volatile("ld.volatile.global.v4.s32 {%0,%1,%2,%3}, [%4];"
                 : "=r"(v.x), "=r"(v.y), "=r"(v.z), "=r"(v.w) : "l"(p) : "memory");
    return v;
}
__device__ __forceinline__ void fence_acq_rel_gpu() {
    asm volatile("fence.acq_rel.gpu;" ::: "memory");
}

// 42 CTAs x 1024 threads (one CTA per SM, single wave):
//   CTA 0..31  : consumer b — fac1 row in smem partials, poll flags,
//                warp-per-class dot, parallel fast softmax, write out[b].
//   CTA 32..41 : producer c — fac2 row, publish slice + release flag.
__global__ __launch_bounds__(NT, 1) void fused_kernel(
    const float* __restrict__ x,
    const float* __restrict__ mu,
    const float* __restrict__ U,
    const float* __restrict__ V,
    float* __restrict__ out) {
    __shared__ float sx[D];
    __shared__ float part[8][K];     // 8 d-groups x 512 (16 KB)
    __shared__ float f1s[K];
    __shared__ float hrow[C];

    const int t    = threadIdx.x;
    const int w    = t >> 5;
    const int lane = t & 31;
    const int g    = t >> 7;         // d-group 0..7 (16 d-rows each)
    const int tt   = t & 127;        // float4 col, full K

    const bool producer = (blockIdx.x >= B);
    const int  row = producer ? (blockIdx.x - B) : blockIdx.x;
    const float* src = producer ? (mu + row * D) : (x + row * D);
    const float* Wg  = (producer ? V : U) + g * 16 * K;

    if (t < D) sx[t] = src[t];

    // front-batched: all 16 LDG.128 in flight before the smem-operand wait
    float4 wv[16];
#pragma unroll
    for (int i = 0; i < 16; i++)
        wv[i] = reinterpret_cast<const float4*>(Wg + i * K)[tt];
    __syncthreads();

    float4 acc = make_float4(0.f, 0.f, 0.f, 0.f);
    const float* sg = sx + g * 16;
#pragma unroll
    for (int i = 0; i < 16; i++) {
        const float sv = sg[i];
        acc.x = fmaf(sv, wv[i].x, acc.x);
        acc.y = fmaf(sv, wv[i].y, acc.y);
        acc.z = fmaf(sv, wv[i].z, acc.z);
        acc.w = fmaf(sv, wv[i].w, acc.w);
    }
    reinterpret_cast<float4*>(&part[g][tt * 4])[0] = acc;
    __syncthreads();

    if (producer) {
        // reduce 8 d-partials, publish fac2 row, release own flag
        if (t < 128) {
            float4 r = make_float4(0.f, 0.f, 0.f, 0.f);
#pragma unroll
            for (int gg = 0; gg < 8; gg++) {
                float4 a = reinterpret_cast<const float4*>(&part[gg][t * 4])[0];
                r.x += a.x; r.y += a.y; r.z += a.z; r.w += a.w;
            }
            reinterpret_cast<float4*>(&g_fac2[row][0])[t] = r;
        }
        __syncthreads();                 // row stores happen-before flag
        if (t == 0) st_release_gpu(&g_pflag[row], 1);
        return;
    }

    // ---------------- consumer ----------------
    // fold d-group partials while thread 0 polls in parallel
    if (t == 0) {
        const int4* fp = reinterpret_cast<const int4*>(g_pflag);
        for (;;) {
            int4 f0 = ld_volatile_v4(fp);
            int4 f1 = ld_volatile_v4(fp + 1);
            int4 f2 = ld_volatile_v4(fp + 2);
            if (f0.x + f0.y + f0.z + f0.w + f1.x + f1.y + f1.z + f1.w +
                f2.x + f2.y + f2.z + f2.w == C) break;
        }
        fence_acq_rel_gpu();
    }
    if (t >= 512 && t < 512 + K) {       // disjoint warps fold while warp 0 polls
        const int k = t - 512;
        float f = part[0][k];
#pragma unroll
        for (int gg = 1; gg < 8; gg++) f += part[gg][k];
        f1s[k] = f;
    }
    __syncthreads();                     // f1s ready AND fac2 visible

    // one warp per class: dot(f1s, fac2[c]) over K=512 (4 float4 per lane)
    if (w < C) {
        const float4* fa = reinterpret_cast<const float4*>(f1s);
        const float4* fb = reinterpret_cast<const float4*>(&g_fac2[w][0]);
        float p = 0.f;
#pragma unroll
        for (int j = 0; j < 4; j++) {
            const int i4 = lane + j * 32;
            float4 a = fa[i4];
            float4 b2 = fb[i4];
            p += a.x * b2.x + a.y * b2.y + a.z * b2.z + a.w * b2.w;
        }
#pragma unroll
        for (int o = 16; o > 0; o >>= 1)
            p += __shfl_xor_sync(0xffffffffu, p, o);
        if (lane == 0) hrow[w] = p;
    }
    __syncthreads();

    // parallel log_softmax in warp 0: lane c owns class c (fast MUFU path)
    if (w == 0) {
        float h = (lane < C) ? hrow[lane] : -INFINITY;
        float m = h;
#pragma unroll
        for (int o = 8; o > 0; o >>= 1)
            m = fmaxf(m, __shfl_xor_sync(0xffffffffu, m, o));
        m = __shfl_sync(0xffffffffu, m, 0);
        float e = (lane < C) ? __expf(h - m) : 0.f;   // MUFU.EX2
        float se = e;
#pragma unroll
        for (int o = 8; o > 0; o >>= 1)
            se += __shfl_xor_sync(0xffffffffu, se, o);
        se = __shfl_sync(0xffffffffu, se, 0);
        const float lse = m + __logf(se);             // MUFU.LG2
        if (lane < C) out[row * C + lane] = h - lse;

        // last consumer resets flags for the next graph replay
        if (lane == 0 && atomicAdd(&g_done, 1) == B - 1) {
#pragma unroll
            for (int j = 0; j < C; j++) g_pflag[j] = 0;
            g_done = 0;
        }
    }
}

extern "C" void kernel_launch(void* const* d_in, const int* in_sizes, int n_in,
                              void* d_out, int out_size) {
    const float* x  = (const float*)d_in[0];  // [32, 128]
    const float* mu = (const float*)d_in[1];  // [10, 128]
    const float* U  = (const float*)d_in[2];  // [128, 512]
    const float* V  = (const float*)d_in[3];  // [128, 512]
    float* out = (float*)d_out;               // [32, 10]

    fused_kernel<<<B + C, NT>>>(x, mu, U, V, out);
}